// round 15
// baseline (speedup 1.0000x reference)
#include <cuda_runtime.h>
#include <math.h>
#include <stdint.h>

#define D       256
#define K       8
#define FULLM   0xffffffffu

typedef unsigned long long u64;

// ---- k_assign (MMA dots + vector scalar accumulate) config ----
#define A_TPB    96
#define A_WPB    3
#define A_GRID   296                  // 2 CTAs/SM * 148
#define A_TOTW   (A_GRID * A_WPB)     // 888 warps
#define AP       68                   // quarter pitch (floats)
#define SLOTF    (16 * AP)            // 1088 floats / slot
#define SLOTB    (SLOTF * 4)          // 4352 B
#define NSLOT    6
// dynamic smem offsets (bytes)
#define OFF_P    0                    // protos [q][k][68] = 8704 B
#define OFF_TILE 8704                 // 3 * 6 * 4352 = 78336 B
#define OFF_ACC  87040                // 3 * 8192 = 24576 B
#define OFF_ICNT 111616               // 24 ints
#define A_SMEM   111712               // x2 CTAs = 218.2 KB/SM

// ---- k_loss (MMA) config — R9 verbatim ----
#define L_TPB   64
#define L_CTAS  740                   // 5 * 148
#define L_TOTW  (L_CTAS * 2)
#define PITCH   260

// ---- device scratch ----
__device__ float g_part_sums[A_GRID * K * D];
__device__ int   g_part_counts[A_GRID * K];
__device__ float g_mid[8 * K * D];
__device__ float g_part_loss[L_CTAS];
__device__ float g_protos_new[K * D];

// ---------------- helpers ----------------
__device__ __forceinline__ u64 pk2(float lo, float hi) {
    u64 r; asm("mov.b64 %0, {%1, %2};" : "=l"(r) : "f"(lo), "f"(hi)); return r;
}
__device__ __forceinline__ u64 ffma2(u64 a, u64 b, u64 c) {
    u64 d; asm("fma.rn.f32x2 %0, %1, %2, %3;" : "=l"(d) : "l"(a), "l"(b), "l"(c)); return d;
}
__device__ __forceinline__ void cp16(uint32_t s, const void* g) {
    asm volatile("cp.async.cg.shared.global [%0], [%1], 16;" :: "r"(s), "l"(g));
}

__device__ __forceinline__ float warp_sum(float v) {
    v += __shfl_xor_sync(FULLM, v, 16);
    v += __shfl_xor_sync(FULLM, v, 8);
    v += __shfl_xor_sync(FULLM, v, 4);
    v += __shfl_xor_sync(FULLM, v, 2);
    v += __shfl_xor_sync(FULLM, v, 1);
    return v;
}

__device__ __forceinline__ void mma_tf32(float& c0, float& c1, float& c2, float& c3,
                                         float a0, float a1, float b) {
    asm volatile(
        "mma.sync.aligned.m16n8k4.row.col.f32.tf32.tf32.f32 "
        "{%0,%1,%2,%3}, {%4,%5}, {%6}, {%0,%1,%2,%3};"
        : "+f"(c0), "+f"(c1), "+f"(c2), "+f"(c3)
        : "r"(__float_as_uint(a0)), "r"(__float_as_uint(a1)), "r"(__float_as_uint(b)));
}

// ============================================================================
// Kernel 1: assignment. MMA dots (R9 engine) + 6-slot ring keeping the whole
// 16-row tile resident; vectorized scalar accumulate into per-warp smem acc.
// ============================================================================
extern __shared__ char dsm[];

__global__ void __launch_bounds__(A_TPB, 2)
k_assign(const float* __restrict__ src, const float* __restrict__ protos, int N)
{
    const int tid  = threadIdx.x;
    const int lane = tid & 31;
    const int warp = tid >> 5;
    const int g    = lane >> 2;   // 0..7
    const int t    = lane & 3;    // 0..3

    float* s_p    = (float*)(dsm + OFF_P);
    float* tile_w = (float*)(dsm + OFF_TILE) + warp * NSLOT * SLOTF;
    float* s_accw = (float*)(dsm + OFF_ACC) + warp * (K * D);
    float* s_accb = (float*)(dsm + OFF_ACC);
    int*   s_icnt = (int*)(dsm + OFF_ICNT);

    // protos -> smem, layout [q][k][68]
    for (int e = tid; e < 4 * K * AP; e += A_TPB) {
        int blk = e / AP, c = e - blk * AP;
        int q = blk >> 3, k = blk & 7;
        s_p[e] = (c < 64) ? protos[k * D + q * 64 + c] : 0.0f;
    }
    for (int e = tid; e < A_WPB * K * D; e += A_TPB) s_accb[e] = 0.0f;
    __syncthreads();

    const uint32_t tbase = (uint32_t)__cvta_generic_to_shared(tile_w);

    const int gw     = blockIdx.x * A_WPB + warp;
    const int ntiles = (N + 15) >> 4;
    const int own    = (gw < ntiles) ? ((ntiles - 1 - gw) / A_TOTW + 1) : 0;
    const int Jmax   = own * 4;

    auto issue = [&](int j) {
        const int slot = j % NSLOT;
        int jd = (j < Jmax) ? j : (Jmax - 1);
        const int tt = gw + (jd >> 2) * A_TOTW;
        const int q  = jd & 3;
        const int row0 = tt << 4;
#pragma unroll
        for (int i = 0; i < 8; i++) {
            int u = i * 32 + lane;
            int r = u >> 4, c4 = u & 15;
            int row = row0 + r; if (row >= N) row = N - 1;
            cp16(tbase + (uint32_t)(slot * SLOTB) + (uint32_t)(r * AP + c4 * 4) * 4,
                 src + (size_t)row * D + q * 64 + c4 * 4);
        }
        asm volatile("cp.async.commit_group;" ::: "memory");
    };

    int cnt = 0;
    float c0 = 0.f, c1 = 0.f, c2 = 0.f, c3 = 0.f, ssg = 0.f, ssh = 0.f;

    // source positions for accumulate: lane covers float cols 4*p1.. / 4*p2..
    const int p1 = lane;        // 0..31
    const int p2 = lane + 32;   // 32..63

    if (Jmax > 0) { issue(0); issue(1); }

    for (int j = 0; j < Jmax; j++) {
        asm volatile("cp.async.wait_group 1;" ::: "memory");
        __syncwarp();
        issue(j + 2);

        const int q    = j & 3;
        const int slot = j % NSLOT;
        const float* A0 = tile_w + slot * SLOTF + g * AP + t;
        const float* A1 = tile_w + slot * SLOTF + (g + 8) * AP + t;
        const float* Bp = s_p + (q * 8 + g) * AP + t;

#pragma unroll
        for (int s = 0; s < 16; s++) {
            float a0 = A0[s * 4];
            float a1 = A1[s * 4];
            float bb = Bp[s * 4];
            ssg = fmaf(a0, a0, ssg);
            ssh = fmaf(a1, a1, ssh);
            mma_tf32(c0, c1, c2, c3, a0, a1, bb);
        }

        if (q == 3) {
            // ---- norms (fp32 exact) ----
            ssg += __shfl_xor_sync(FULLM, ssg, 1);
            ssg += __shfl_xor_sync(FULLM, ssg, 2);
            ssh += __shfl_xor_sync(FULLM, ssh, 1);
            ssh += __shfl_xor_sync(FULLM, ssh, 2);
            const float inv0 = rsqrtf(fmaxf(ssg, 1e-24f));
            const float inv1 = rsqrtf(fmaxf(ssh, 1e-24f));

            // ---- per-row argmax, first-max tiebreak ----
            float lv0 = c0; int lb0 = 2 * t;
            if (c1 > lv0) { lv0 = c1; lb0 = 2 * t + 1; }
            float lv1 = c2; int lb1 = 2 * t;
            if (c3 > lv1) { lv1 = c3; lb1 = 2 * t + 1; }
#pragma unroll
            for (int s = 1; s <= 2; s <<= 1) {
                float ov0 = __shfl_xor_sync(FULLM, lv0, s);
                int   ok0 = __shfl_xor_sync(FULLM, lb0, s);
                if (ov0 > lv0 || (ov0 == lv0 && ok0 < lb0)) { lv0 = ov0; lb0 = ok0; }
                float ov1 = __shfl_xor_sync(FULLM, lv1, s);
                int   ok1 = __shfl_xor_sync(FULLM, lb1, s);
                if (ov1 > lv1 || (ov1 == lv1 && ok1 < lb1)) { lv1 = ov1; lb1 = ok1; }
            }

            const int tt   = gw + (j >> 2) * A_TOTW;
            const int row0 = tt << 4;

            // tile quarters live in slots (j-3+qq) % 6
            const float* T1 = tile_w + ((j - 3 + (p1 >> 4)) % NSLOT) * SLOTF + (p1 & 15) * 4;
            const float* T2 = tile_w + ((j - 3 + (p2 >> 4)) % NSLOT) * SLOTF + (p2 & 15) * 4;

#pragma unroll
            for (int r2 = 0; r2 < 16; r2++) {
                const int row = row0 + r2;
                if (row < N) {
                    const int   srcl = (r2 & 7) * 4;
                    const int   bk   = (r2 < 8) ? __shfl_sync(FULLM, lb0, srcl)
                                                : __shfl_sync(FULLM, lb1, srcl);
                    const float inv  = (r2 < 8) ? __shfl_sync(FULLM, inv0, srcl)
                                                : __shfl_sync(FULLM, inv1, srcl);
                    cnt += (bk == (lane & 7));
                    const u64 iv = pk2(inv, inv);
                    const ulonglong2 x1 = *(const ulonglong2*)(T1 + r2 * AP);
                    const ulonglong2 x2 = *(const ulonglong2*)(T2 + r2 * AP);
                    ulonglong2* a1p = (ulonglong2*)(s_accw + bk * D + 4 * lane);
                    ulonglong2* a2p = (ulonglong2*)(s_accw + bk * D + 128 + 4 * lane);
                    ulonglong2 v1 = *a1p;
                    v1.x = ffma2(x1.x, iv, v1.x);
                    v1.y = ffma2(x1.y, iv, v1.y);
                    *a1p = v1;
                    ulonglong2 v2 = *a2p;
                    v2.x = ffma2(x2.x, iv, v2.x);
                    v2.y = ffma2(x2.y, iv, v2.y);
                    *a2p = v2;
                }
            }
            __syncwarp();

            c0 = c1 = c2 = c3 = 0.f;
            ssg = ssh = 0.f;
        }
    }

    asm volatile("cp.async.wait_group 0;" ::: "memory");
    __syncwarp();

    // counts (4x inflated; cancels in normalize downstream)
    cnt += __shfl_xor_sync(FULLM, cnt, 8);
    cnt += __shfl_xor_sync(FULLM, cnt, 16);
    if (lane < K) s_icnt[warp * K + lane] = cnt;
    __syncthreads();

    for (int e = tid; e < K * D; e += A_TPB) {
        g_part_sums[blockIdx.x * (K * D) + e] =
            s_accb[e] + s_accb[e + K * D] + s_accb[e + 2 * K * D];
    }
    if (tid < K) {
        g_part_counts[blockIdx.x * K + tid] =
            s_icnt[tid] + s_icnt[K + tid] + s_icnt[2 * K + tid];
    }
}

// ============================================================================
// Kernel 2: reduce A_GRID (296) partial blocks -> 8 mid blocks
// ============================================================================
#define RCHUNK 37   // 296 / 8
__global__ void k_reduce1()
{
    const int be = blockIdx.x & 7;
    const int bb = blockIdx.x >> 3;
    const int e  = be * 256 + threadIdx.x;
    float s = 0.0f;
    const int b0 = bb * RCHUNK;
    const int b1 = min(b0 + RCHUNK, A_GRID);
    for (int b = b0; b < b1; b++) s += g_part_sums[b * (K * D) + e];
    g_mid[bb * (K * D) + e] = s;
}

// ============================================================================
// Kernel 3: final reduce + prototype EMA update + renormalize (1 block)
// ============================================================================
__global__ void k_update(const float* __restrict__ protos)
{
    __shared__ float s_sums[K * D];
    __shared__ int   s_cnt[K];

    const int tid  = threadIdx.x;
    const int lane = tid & 31;
    const int warp = tid >> 5;

    for (int e = tid; e < K * D; e += 256) {
        float s = 0.0f;
#pragma unroll
        for (int m = 0; m < 8; m++) s += g_mid[m * (K * D) + e];
        s_sums[e] = s;
    }
    {
        int c = 0;
        for (int b = lane; b < A_GRID; b += 32) c += g_part_counts[b * K + warp];
        c = __reduce_add_sync(FULLM, c);
        if (lane == 0) s_cnt[warp] = c;
    }
    __syncthreads();

    const int k = warp;
    const float4* s4 = (const float4*)s_sums;
    float4 s1 = s4[k * 64 + lane];
    float4 s2 = s4[k * 64 + 32 + lane];

    const int   c = s_cnt[k];
    const float rr = 1.0f / fmaxf((float)c, 1.0f);
    float4 m1 = make_float4(s1.x*rr, s1.y*rr, s1.z*rr, s1.w*rr);
    float4 m2 = make_float4(s2.x*rr, s2.y*rr, s2.z*rr, s2.w*rr);

    float ss = m1.x*m1.x + m1.y*m1.y + m1.z*m1.z + m1.w*m1.w
             + m2.x*m2.x + m2.y*m2.y + m2.z*m2.z + m2.w*m2.w;
    ss = warp_sum(ss);
    const float inv = 1.0f / fmaxf(sqrtf(ss), 1e-12f);

    const float4* p4 = (const float4*)protos;
    const float4 p1 = p4[k * 64 + lane];
    const float4 p2 = p4[k * 64 + 32 + lane];

    float4 u1, u2;
    if (c > 0) {
        u1 = make_float4(0.9f*p1.x + 0.1f*m1.x*inv, 0.9f*p1.y + 0.1f*m1.y*inv,
                         0.9f*p1.z + 0.1f*m1.z*inv, 0.9f*p1.w + 0.1f*m1.w*inv);
        u2 = make_float4(0.9f*p2.x + 0.1f*m2.x*inv, 0.9f*p2.y + 0.1f*m2.y*inv,
                         0.9f*p2.z + 0.1f*m2.z*inv, 0.9f*p2.w + 0.1f*m2.w*inv);
    } else {
        u1 = p1; u2 = p2;
    }

    float ss2 = u1.x*u1.x + u1.y*u1.y + u1.z*u1.z + u1.w*u1.w
              + u2.x*u2.x + u2.y*u2.y + u2.z*u2.z + u2.w*u2.w;
    ss2 = warp_sum(ss2);
    const float inv2 = 1.0f / fmaxf(sqrtf(ss2), 1e-12f);

    float4* o4 = (float4*)g_protos_new;
    o4[k * 64 + lane]      = make_float4(u1.x*inv2, u1.y*inv2, u1.z*inv2, u1.w*inv2);
    o4[k * 64 + 32 + lane] = make_float4(u2.x*inv2, u2.y*inv2, u2.z*inv2, u2.w*inv2);
}

// ============================================================================
// Kernel 4 (R9 verbatim): target loss via tf32 MMA, 4-slot quarter ring
// ============================================================================
__global__ void __launch_bounds__(L_TPB, 5)
k_loss(const float* __restrict__ tgt, int N)
{
    __shared__ float s_p[K * PITCH];
    __shared__ float s_tile[2][16 * PITCH];
    __shared__ float s_l[2];

    const int tid  = threadIdx.x;
    const int lane = tid & 31;
    const int warp = tid >> 5;
    const int g    = lane >> 2;
    const int t    = lane & 3;

    for (int e = tid; e < K * PITCH; e += L_TPB) {
        int k = e / PITCH, c = e - k * PITCH;
        s_p[e] = (c < D) ? g_protos_new[k * D + c] : 0.0f;
    }
    __syncthreads();

    const int gw     = blockIdx.x * 2 + warp;
    const int ntiles = (N + 15) >> 4;
    const int own    = (gw < ntiles) ? ((ntiles - 1 - gw) / L_TOTW + 1) : 0;
    const int Jmax   = own * 4;

    float* tile = s_tile[warp];
    const uint32_t tbase = (uint32_t)__cvta_generic_to_shared(tile);

    auto issue = [&](int j) {
        const int slot = j & 3;
        int jd = (j < Jmax) ? j : (Jmax - 1);
        const int tt = gw + (jd >> 2) * L_TOTW;
        const int q  = jd & 3;
        const int row0 = tt << 4;
#pragma unroll
        for (int i = 0; i < 8; i++) {
            int u = i * 32 + lane;
            int r = u >> 4, c = u & 15;
            int row = row0 + r; if (row >= N) row = N - 1;
            cp16(tbase + (uint32_t)(r * PITCH + slot * 64 + c * 4) * 4,
                 tgt + (size_t)row * D + q * 64 + c * 4);
        }
        asm volatile("cp.async.commit_group;" ::: "memory");
    };

    float lsum = 0.0f;
    float c0 = 0.f, c1 = 0.f, c2 = 0.f, c3 = 0.f, ssg = 0.f, ssh = 0.f;

    if (Jmax > 0) { issue(0); issue(1); }

    for (int j = 0; j < Jmax; j++) {
        asm volatile("cp.async.wait_group 1;" ::: "memory");
        __syncwarp();
        issue(j + 2);

        const int q = j & 3;
        const float* A0 = tile + g * PITCH + q * 64 + t;
        const float* A1 = tile + (g + 8) * PITCH + q * 64 + t;
        const float* Bp = s_p + g * PITCH + q * 64 + t;

#pragma unroll
        for (int s = 0; s < 16; s++) {
            float a0 = A0[s * 4];
            float a1 = A1[s * 4];
            float bb = Bp[s * 4];
            ssg = fmaf(a0, a0, ssg);
            ssh = fmaf(a1, a1, ssh);
            mma_tf32(c0, c1, c2, c3, a0, a1, bb);
        }

        if (q == 3) {
            ssg += __shfl_xor_sync(FULLM, ssg, 1);
            ssg += __shfl_xor_sync(FULLM, ssg, 2);
            ssh += __shfl_xor_sync(FULLM, ssh, 1);
            ssh += __shfl_xor_sync(FULLM, ssh, 2);
            float m0 = fmaxf(c0, c1);
            float m1 = fmaxf(c2, c3);
            m0 = fmaxf(m0, __shfl_xor_sync(FULLM, m0, 1));
            m0 = fmaxf(m0, __shfl_xor_sync(FULLM, m0, 2));
            m1 = fmaxf(m1, __shfl_xor_sync(FULLM, m1, 1));
            m1 = fmaxf(m1, __shfl_xor_sync(FULLM, m1, 2));

            const int tt = gw + (j >> 2) * L_TOTW;
            const int row0 = tt << 4;
            if (t == 0) {
                if (row0 + g < N)     lsum += m0 * rsqrtf(fmaxf(ssg, 1e-24f));
                if (row0 + 8 + g < N) lsum += m1 * rsqrtf(fmaxf(ssh, 1e-24f));
            }
            c0 = c1 = c2 = c3 = 0.f;
            ssg = ssh = 0.f;
        }
    }

    lsum = warp_sum(lsum);
    if (lane == 0) s_l[warp] = lsum;
    __syncthreads();
    if (tid == 0) g_part_loss[blockIdx.x] = s_l[0] + s_l[1];
}

// ============================================================================
// Kernel 5: final mean:  out = 1 - (sum of max cos) / Nt
// ============================================================================
__global__ void k_final(float* __restrict__ out, int Nt)
{
    __shared__ float sw[16];
    const int tid  = threadIdx.x;
    const int lane = tid & 31;
    const int warp = tid >> 5;

    float v = 0.0f;
    for (int i = tid; i < L_CTAS; i += 512) v += g_part_loss[i];
    v = warp_sum(v);
    if (lane == 0) sw[warp] = v;
    __syncthreads();
    if (tid == 0) {
        float s = 0.0f;
#pragma unroll
        for (int w = 0; w < 16; w++) s += sw[w];
        out[0] = 1.0f - s / (float)Nt;
    }
}

// ============================================================================
extern "C" void kernel_launch(void* const* d_in, const int* in_sizes, int n_in,
                              void* d_out, int out_size)
{
    const float* src    = (const float*)d_in[0];
    const float* tgt    = (const float*)d_in[1];
    const float* protos = (const float*)d_in[2];
    float* out = (float*)d_out;

    const int Ns = in_sizes[0] / D;
    const int Nt = in_sizes[1] / D;

    cudaFuncSetAttribute(k_assign, cudaFuncAttributeMaxDynamicSharedMemorySize, A_SMEM);

    k_assign<<<A_GRID, A_TPB, A_SMEM>>>(src, protos, Ns);
    k_reduce1<<<64, 256>>>();
    k_update<<<1, 256>>>(protos);
    k_loss<<<L_CTAS, L_TPB>>>(tgt, Nt);
    k_final<<<1, 512>>>(out, Nt);
}

// round 16
// speedup vs baseline: 1.1122x; 1.1122x over previous
#include <cuda_runtime.h>
#include <math.h>
#include <stdint.h>

#define D       256
#define K       8
#define FULLM   0xffffffffu

// ---- k_assign config (R5 structure) ----
#define A_TPB   128
#define A_WPB   4
#define A_GRID  444          // 3 * 148
#define NWARPS  (A_GRID * A_WPB)

// ---- k_loss (MMA) config — R9 verbatim ----
#define L_TPB   64
#define L_CTAS  740          // 5 * 148
#define L_TOTW  (L_CTAS * 2)
#define PITCH   260          // floats; conflict-free frag LDS

typedef unsigned long long u64;

// ---- device scratch (no allocations allowed) ----
__device__ float g_part_sums[A_GRID * K * D];
__device__ int   g_part_counts[A_GRID * K];
__device__ float g_mid[8 * K * D];
__device__ float g_part_loss[L_CTAS];
__device__ float g_protos_new[K * D];

// ---------------- f32x2 packed helpers ----------------
__device__ __forceinline__ u64 pk2(float lo, float hi) {
    u64 r; asm("mov.b64 %0, {%1, %2};" : "=l"(r) : "f"(lo), "f"(hi)); return r;
}
__device__ __forceinline__ float hadd2(u64 v) {
    float lo, hi; asm("mov.b64 {%0, %1}, %2;" : "=f"(lo), "=f"(hi) : "l"(v));
    return lo + hi;
}
__device__ __forceinline__ u64 mul2(u64 a, u64 b) {
    u64 d; asm("mul.rn.f32x2 %0, %1, %2;" : "=l"(d) : "l"(a), "l"(b)); return d;
}
__device__ __forceinline__ u64 ffma2(u64 a, u64 b, u64 c) {
    u64 d; asm("fma.rn.f32x2 %0, %1, %2, %3;" : "=l"(d) : "l"(a), "l"(b), "l"(c)); return d;
}
__device__ __forceinline__ void cp16(uint32_t s, const void* g) {
    asm volatile("cp.async.cg.shared.global [%0], [%1], 16;" :: "r"(s), "l"(g));
}

__device__ __forceinline__ float warp_sum(float v) {
    v += __shfl_xor_sync(FULLM, v, 16);
    v += __shfl_xor_sync(FULLM, v, 8);
    v += __shfl_xor_sync(FULLM, v, 4);
    v += __shfl_xor_sync(FULLM, v, 2);
    v += __shfl_xor_sync(FULLM, v, 1);
    return v;
}

// Folded 8-value warp reduction: lane l holds full sum of k = (l>>2)&7.
__device__ __forceinline__ float fold8(const float* v, int lane) {
    float v0, v1, v2, v3;
    {
        bool hi = (lane & 16) != 0;
        float k0 = hi ? v[4] : v[0], k1 = hi ? v[5] : v[1];
        float k2 = hi ? v[6] : v[2], k3 = hi ? v[7] : v[3];
        float s0 = hi ? v[0] : v[4], s1 = hi ? v[1] : v[5];
        float s2 = hi ? v[2] : v[6], s3 = hi ? v[3] : v[7];
        v0 = k0 + __shfl_xor_sync(FULLM, s0, 16);
        v1 = k1 + __shfl_xor_sync(FULLM, s1, 16);
        v2 = k2 + __shfl_xor_sync(FULLM, s2, 16);
        v3 = k3 + __shfl_xor_sync(FULLM, s3, 16);
    }
    {
        bool hi = (lane & 8) != 0;
        float k0 = hi ? v2 : v0, k1 = hi ? v3 : v1;
        float s0 = hi ? v0 : v2, s1 = hi ? v1 : v3;
        v0 = k0 + __shfl_xor_sync(FULLM, s0, 8);
        v1 = k1 + __shfl_xor_sync(FULLM, s1, 8);
    }
    {
        bool hi = (lane & 4) != 0;
        float k0 = hi ? v1 : v0;
        float s0 = hi ? v0 : v1;
        v0 = k0 + __shfl_xor_sync(FULLM, s0, 4);
    }
    v0 += __shfl_xor_sync(FULLM, v0, 2);
    v0 += __shfl_xor_sync(FULLM, v0, 1);
    return v0;
}

__device__ __forceinline__ void dots8(const ulonglong2& A, const ulonglong2& B,
                                      const ulonglong2* PA, const ulonglong2* PB,
                                      float* v, float& ssout)
{
    u64 ss2 = mul2(A.x, A.x);
    ss2 = ffma2(A.y, A.y, ss2);
    ss2 = ffma2(B.x, B.x, ss2);
    ss2 = ffma2(B.y, B.y, ss2);
#pragma unroll
    for (int k = 0; k < K; k++) {
        u64 d = mul2(A.x, PA[k].x);
        d = ffma2(A.y, PA[k].y, d);
        d = ffma2(B.x, PB[k].x, d);
        d = ffma2(B.y, PB[k].y, d);
        v[k] = hadd2(d);
    }
    ssout = hadd2(ss2);
}

// Ballot argmax with first-max tiebreak. dv per fold8 layout: lane l holds
// the sum for k = l >> 2; lowest matching lane <=> lowest k.
__device__ __forceinline__ int argmax8_ballot(float dv)
{
    float m = dv;
    m = fmaxf(m, __shfl_xor_sync(FULLM, m, 4));
    m = fmaxf(m, __shfl_xor_sync(FULLM, m, 8));
    m = fmaxf(m, __shfl_xor_sync(FULLM, m, 16));
    unsigned mask = __ballot_sync(FULLM, dv == m);
    return (__ffs(mask) - 1) >> 2;
}

// ============================================================================
// Kernel 1: assignment + per-cluster normalized sums (scalar, ballot argmax)
// ============================================================================
__global__ void __launch_bounds__(A_TPB, 3)
k_assign(const float* __restrict__ src, const float* __restrict__ protos, int N)
{
    __shared__ float s_acc[A_WPB * K * D];   // 32 KB: [warp][k][col]
    __shared__ int   s_icnt[A_WPB * K];

    const int tid  = threadIdx.x;
    const int lane = tid & 31;
    const int warp = tid >> 5;

    for (int e = tid; e < A_WPB * K * D; e += A_TPB) s_acc[e] = 0.0f;

    const ulonglong2* up = (const ulonglong2*)protos;
    ulonglong2 PA[K], PB[K];
#pragma unroll
    for (int k = 0; k < K; k++) {
        PA[k] = up[k * 64 + lane];
        PB[k] = up[k * 64 + 32 + lane];
    }
    __syncthreads();

    int cnt = 0;

    const int gw      = blockIdx.x * A_WPB + warp;
    const int Npair   = N & ~1;
    const int stride2 = NWARPS * 2;

    int base = gw * 2;
    ulonglong2 A0, B0, A1, B1;
    if (base < Npair) {
        const ulonglong2* rp = (const ulonglong2*)src + (size_t)base * 64;
        A0 = rp[lane];        B0 = rp[lane + 32];
        A1 = rp[64 + lane];   B1 = rp[64 + lane + 32];
    }

    while (base < Npair) {
        const int nbase = base + stride2;
        ulonglong2 An0 = A0, Bn0 = B0, An1 = A1, Bn1 = B1;
        if (nbase < Npair) {
            const ulonglong2* np = (const ulonglong2*)src + (size_t)nbase * 64;
            An0 = np[lane];        Bn0 = np[lane + 32];
            An1 = np[64 + lane];   Bn1 = np[64 + lane + 32];
        }

        float v0[K], v1[K], ssa, ssb;
        dots8(A0, B0, PA, PB, v0, ssa);
        dots8(A1, B1, PA, PB, v1, ssb);

        float dv0 = fold8(v0, lane);
        float dv1 = fold8(v1, lane);
        float ss0 = warp_sum(ssa);
        float ss1 = warp_sum(ssb);

        const float inv0 = rsqrtf(fmaxf(ss0, 1e-24f));
        const float inv1 = rsqrtf(fmaxf(ss1, 1e-24f));

        const int bk0 = argmax8_ballot(dv0);
        const int bk1 = argmax8_ballot(dv1);

        cnt += (bk0 == (lane & 7)) + (bk1 == (lane & 7));

        {
            const u64 iv = pk2(inv0, inv0);
            ulonglong2* ap = (ulonglong2*)(s_acc + (warp * K + bk0) * D) + lane;
            ulonglong2 c0 = ap[0];
            c0.x = ffma2(A0.x, iv, c0.x);
            c0.y = ffma2(A0.y, iv, c0.y);
            ap[0] = c0;
            ulonglong2 c1 = ap[32];
            c1.x = ffma2(B0.x, iv, c1.x);
            c1.y = ffma2(B0.y, iv, c1.y);
            ap[32] = c1;
        }
        {
            const u64 iv = pk2(inv1, inv1);
            ulonglong2* ap = (ulonglong2*)(s_acc + (warp * K + bk1) * D) + lane;
            ulonglong2 c0 = ap[0];
            c0.x = ffma2(A1.x, iv, c0.x);
            c0.y = ffma2(A1.y, iv, c0.y);
            ap[0] = c0;
            ulonglong2 c1 = ap[32];
            c1.x = ffma2(B1.x, iv, c1.x);
            c1.y = ffma2(B1.y, iv, c1.y);
            ap[32] = c1;
        }

        A0 = An0; B0 = Bn0; A1 = An1; B1 = Bn1;
        base = nbase;
    }

    if ((N & 1) && gw == 0) {
        const int row = N - 1;
        const ulonglong2* rp = (const ulonglong2*)src + (size_t)row * 64;
        ulonglong2 A = rp[lane], B = rp[lane + 32];
        float v[K], ssp;
        dots8(A, B, PA, PB, v, ssp);
        float dv = fold8(v, lane);
        float ss = warp_sum(ssp);
        const float inv = rsqrtf(fmaxf(ss, 1e-24f));
        const int bk = argmax8_ballot(dv);
        cnt += (bk == (lane & 7));
        const u64 iv = pk2(inv, inv);
        ulonglong2* ap = (ulonglong2*)(s_acc + (warp * K + bk) * D) + lane;
        ulonglong2 c0 = ap[0];
        c0.x = ffma2(A.x, iv, c0.x);
        c0.y = ffma2(A.y, iv, c0.y);
        ap[0] = c0;
        ulonglong2 c1 = ap[32];
        c1.x = ffma2(B.x, iv, c1.x);
        c1.y = ffma2(B.y, iv, c1.y);
        ap[32] = c1;
    }

    cnt += __shfl_xor_sync(FULLM, cnt, 8);
    cnt += __shfl_xor_sync(FULLM, cnt, 16);
    if (lane < K) s_icnt[warp * K + lane] = cnt;
    __syncthreads();

    for (int e = tid; e < K * D; e += A_TPB) {
        float s = s_acc[e] + s_acc[e + K * D] + s_acc[e + 2 * K * D] + s_acc[e + 3 * K * D];
        g_part_sums[blockIdx.x * (K * D) + e] = s;
    }
    if (tid < K) {
        int c = 0;
#pragma unroll
        for (int w = 0; w < A_WPB; w++) c += s_icnt[w * K + tid];
        g_part_counts[blockIdx.x * K + tid] = c;
    }
}

// ============================================================================
// Kernel 2: reduce A_GRID partial blocks -> 8 mid blocks
// ============================================================================
#define RCHUNK 56   // ceil(444 / 8)
__global__ void k_reduce1()
{
    const int be = blockIdx.x & 7;
    const int bb = blockIdx.x >> 3;
    const int e  = be * 256 + threadIdx.x;
    float s = 0.0f;
    const int b0 = bb * RCHUNK;
    const int b1 = min(b0 + RCHUNK, A_GRID);
    for (int b = b0; b < b1; b++) s += g_part_sums[b * (K * D) + e];
    g_mid[bb * (K * D) + e] = s;
}

// ============================================================================
// Kernel 3: final reduce + prototype EMA update + renormalize (1 block)
// ============================================================================
__global__ void k_update(const float* __restrict__ protos)
{
    __shared__ float s_sums[K * D];
    __shared__ int   s_cnt[K];

    const int tid  = threadIdx.x;
    const int lane = tid & 31;
    const int warp = tid >> 5;

    for (int e = tid; e < K * D; e += 256) {
        float s = 0.0f;
#pragma unroll
        for (int m = 0; m < 8; m++) s += g_mid[m * (K * D) + e];
        s_sums[e] = s;
    }
    {
        int c = 0;
        for (int b = lane; b < A_GRID; b += 32) c += g_part_counts[b * K + warp];
        c = __reduce_add_sync(FULLM, c);
        if (lane == 0) s_cnt[warp] = c;
    }
    __syncthreads();

    const int k = warp;
    const float4* s4 = (const float4*)s_sums;
    float4 s1 = s4[k * 64 + lane];
    float4 s2 = s4[k * 64 + 32 + lane];

    const int   c = s_cnt[k];
    const float rr = 1.0f / fmaxf((float)c, 1.0f);
    float4 m1 = make_float4(s1.x*rr, s1.y*rr, s1.z*rr, s1.w*rr);
    float4 m2 = make_float4(s2.x*rr, s2.y*rr, s2.z*rr, s2.w*rr);

    float ss = m1.x*m1.x + m1.y*m1.y + m1.z*m1.z + m1.w*m1.w
             + m2.x*m2.x + m2.y*m2.y + m2.z*m2.z + m2.w*m2.w;
    ss = warp_sum(ss);
    const float inv = 1.0f / fmaxf(sqrtf(ss), 1e-12f);

    const float4* p4 = (const float4*)protos;
    const float4 p1 = p4[k * 64 + lane];
    const float4 p2 = p4[k * 64 + 32 + lane];

    float4 u1, u2;
    if (c > 0) {
        u1 = make_float4(0.9f*p1.x + 0.1f*m1.x*inv, 0.9f*p1.y + 0.1f*m1.y*inv,
                         0.9f*p1.z + 0.1f*m1.z*inv, 0.9f*p1.w + 0.1f*m1.w*inv);
        u2 = make_float4(0.9f*p2.x + 0.1f*m2.x*inv, 0.9f*p2.y + 0.1f*m2.y*inv,
                         0.9f*p2.z + 0.1f*m2.z*inv, 0.9f*p2.w + 0.1f*m2.w*inv);
    } else {
        u1 = p1; u2 = p2;
    }

    float ss2 = u1.x*u1.x + u1.y*u1.y + u1.z*u1.z + u1.w*u1.w
              + u2.x*u2.x + u2.y*u2.y + u2.z*u2.z + u2.w*u2.w;
    ss2 = warp_sum(ss2);
    const float inv2 = 1.0f / fmaxf(sqrtf(ss2), 1e-12f);

    float4* o4 = (float4*)g_protos_new;
    o4[k * 64 + lane]      = make_float4(u1.x*inv2, u1.y*inv2, u1.z*inv2, u1.w*inv2);
    o4[k * 64 + 32 + lane] = make_float4(u2.x*inv2, u2.y*inv2, u2.z*inv2, u2.w*inv2);
}

// ============================================================================
// Kernel 4 (R9 verbatim): target loss via tf32 MMA, 4-slot quarter ring
// ============================================================================
__global__ void __launch_bounds__(L_TPB, 5)
k_loss(const float* __restrict__ tgt, int N)
{
    __shared__ float s_p[K * PITCH];
    __shared__ float s_tile[2][16 * PITCH];
    __shared__ float s_l[2];

    const int tid  = threadIdx.x;
    const int lane = tid & 31;
    const int warp = tid >> 5;
    const int g    = lane >> 2;
    const int t    = lane & 3;

    for (int e = tid; e < K * PITCH; e += L_TPB) {
        int k = e / PITCH, c = e - k * PITCH;
        s_p[e] = (c < D) ? g_protos_new[k * D + c] : 0.0f;
    }
    __syncthreads();

    const int gw     = blockIdx.x * 2 + warp;
    const int ntiles = (N + 15) >> 4;
    const int own    = (gw < ntiles) ? ((ntiles - 1 - gw) / L_TOTW + 1) : 0;
    const int Jmax   = own * 4;

    float* tile = s_tile[warp];
    const uint32_t tbase = (uint32_t)__cvta_generic_to_shared(tile);

    auto issue = [&](int j) {
        const int slot = j & 3;
        int jd = (j < Jmax) ? j : (Jmax - 1);
        const int tt = gw + (jd >> 2) * L_TOTW;
        const int q  = jd & 3;
        const int row0 = tt << 4;
#pragma unroll
        for (int i = 0; i < 8; i++) {
            int u = i * 32 + lane;
            int r = u >> 4, c = u & 15;
            int row = row0 + r; if (row >= N) row = N - 1;
            cp16(tbase + (uint32_t)(r * PITCH + slot * 64 + c * 4) * 4,
                 tgt + (size_t)row * D + q * 64 + c * 4);
        }
        asm volatile("cp.async.commit_group;" ::: "memory");
    };

    float lsum = 0.0f;
    float c0 = 0.f, c1 = 0.f, c2 = 0.f, c3 = 0.f, ssg = 0.f, ssh = 0.f;

    if (Jmax > 0) { issue(0); issue(1); }

    for (int j = 0; j < Jmax; j++) {
        asm volatile("cp.async.wait_group 1;" ::: "memory");
        __syncwarp();
        issue(j + 2);

        const int q = j & 3;
        const float* A0 = tile + g * PITCH + q * 64 + t;
        const float* A1 = tile + (g + 8) * PITCH + q * 64 + t;
        const float* Bp = s_p + g * PITCH + q * 64 + t;

#pragma unroll
        for (int s = 0; s < 16; s++) {
            float a0 = A0[s * 4];
            float a1 = A1[s * 4];
            float bb = Bp[s * 4];
            ssg = fmaf(a0, a0, ssg);
            ssh = fmaf(a1, a1, ssh);
            asm volatile(
                "mma.sync.aligned.m16n8k4.row.col.f32.tf32.tf32.f32 "
                "{%0,%1,%2,%3}, {%4,%5}, {%6}, {%0,%1,%2,%3};"
                : "+f"(c0), "+f"(c1), "+f"(c2), "+f"(c3)
                : "r"(__float_as_uint(a0)), "r"(__float_as_uint(a1)),
                  "r"(__float_as_uint(bb)));
        }

        if (q == 3) {
            ssg += __shfl_xor_sync(FULLM, ssg, 1);
            ssg += __shfl_xor_sync(FULLM, ssg, 2);
            ssh += __shfl_xor_sync(FULLM, ssh, 1);
            ssh += __shfl_xor_sync(FULLM, ssh, 2);
            float m0 = fmaxf(c0, c1);
            float m1 = fmaxf(c2, c3);
            m0 = fmaxf(m0, __shfl_xor_sync(FULLM, m0, 1));
            m0 = fmaxf(m0, __shfl_xor_sync(FULLM, m0, 2));
            m1 = fmaxf(m1, __shfl_xor_sync(FULLM, m1, 1));
            m1 = fmaxf(m1, __shfl_xor_sync(FULLM, m1, 2));

            const int tt = gw + (j >> 2) * L_TOTW;
            const int row0 = tt << 4;
            if (t == 0) {
                if (row0 + g < N)     lsum += m0 * rsqrtf(fmaxf(ssg, 1e-24f));
                if (row0 + 8 + g < N) lsum += m1 * rsqrtf(fmaxf(ssh, 1e-24f));
            }
            c0 = c1 = c2 = c3 = 0.f;
            ssg = ssh = 0.f;
        }
    }

    lsum = warp_sum(lsum);
    if (lane == 0) s_l[warp] = lsum;
    __syncthreads();
    if (tid == 0) g_part_loss[blockIdx.x] = s_l[0] + s_l[1];
}

// ============================================================================
// Kernel 5: final mean:  out = 1 - (sum of max cos) / Nt
// ============================================================================
__global__ void k_final(float* __restrict__ out, int Nt)
{
    __shared__ float sw[16];
    const int tid  = threadIdx.x;
    const int lane = tid & 31;
    const int warp = tid >> 5;

    float v = 0.0f;
    for (int i = tid; i < L_CTAS; i += 512) v += g_part_loss[i];
    v = warp_sum(v);
    if (lane == 0) sw[warp] = v;
    __syncthreads();
    if (tid == 0) {
        float s = 0.0f;
#pragma unroll
        for (int w = 0; w < 16; w++) s += sw[w];
        out[0] = 1.0f - s / (float)Nt;
    }
}

// ============================================================================
extern "C" void kernel_launch(void* const* d_in, const int* in_sizes, int n_in,
                              void* d_out, int out_size)
{
    const float* src    = (const float*)d_in[0];
    const float* tgt    = (const float*)d_in[1];
    const float* protos = (const float*)d_in[2];
    float* out = (float*)d_out;

    const int Ns = in_sizes[0] / D;
    const int Nt = in_sizes[1] / D;

    k_assign<<<A_GRID, A_TPB>>>(src, protos, Ns);
    k_reduce1<<<64, 256>>>();
    k_update<<<1, 256>>>(protos);
    k_loss<<<L_CTAS, L_TPB>>>(tgt, Nt);
    k_final<<<1, 512>>>(out, Nt);
}